// round 12
// baseline (speedup 1.0000x reference)
#include <cuda_runtime.h>
#include <cuda_bf16.h>
#include <math.h>

#define BB 4
#define CC 64
#define NN 64

typedef unsigned long long ull;

// ---------------------------------------------------------------------------
// Device scratch
// ---------------------------------------------------------------------------
__device__ float2 g_G[BB * NN * 3 * CC * CC];   // 25.2 MB: G[b][v][kh][i][j]
__device__ float  g_part[BB * NN * NN];         // weighted per-frequency logdets

// ---------------------------------------------------------------------------
// f32x2 packed helpers
// ---------------------------------------------------------------------------
__device__ __forceinline__ ull pk2(float lo, float hi) {
    ull r; asm("mov.b64 %0, {%1,%2};" : "=l"(r) : "f"(lo), "f"(hi)); return r;
}
__device__ __forceinline__ void upk2(ull v, float &lo, float &hi) {
    asm("mov.b64 {%0,%1}, %2;" : "=f"(lo), "=f"(hi) : "l"(v));
}
__device__ __forceinline__ ull fma2(ull a, ull b, ull c) {
    ull r; asm("fma.rn.f32x2 %0, %1, %2, %3;" : "=l"(r) : "l"(a), "l"(b), "l"(c));
    return r;
}
__device__ __forceinline__ ull sel4(ull a0, ull a1, ull a2, ull a3, int s) {
    ull x01 = (s & 1) ? a1 : a0;
    ull x23 = (s & 1) ? a3 : a2;
    return (s & 2) ? x23 : x01;
}

// ---------------------------------------------------------------------------
// Kernel 1: G build. G[b,v,kh,i,j] = sum_kw Kfull[b,i,j,kh,kw] * e^{-2pi i v kw/64}
// ---------------------------------------------------------------------------
__global__ __launch_bounds__(256) void gbuild_kernel(const float* __restrict__ K) {
    int v = blockIdx.x & 63;
    int b = blockIdx.x >> 6;
    float th = -6.283185307179586f * (float)v / 64.0f;
    float s1, c1;
    sincosf(th, &s1, &c1);
    float c2 = c1 * c1 - s1 * s1;
    float s2 = 2.0f * s1 * c1;
    long long base = ((long long)(b * 64 + v)) * 3 * 4096;
    for (int e = threadIdx.x; e < 4096; e += 256) {
        int i = e >> 6, j = e & 63;
        const float* kp = K + ((size_t)(b * 64 + i) * 64 + j) * 9;
        float k[9];
#pragma unroll
        for (int t = 0; t < 9; t++) k[t] = kp[t];
        if (i == j) k[4] += 1.0f;
#pragma unroll
        for (int kh = 0; kh < 3; kh++) {
            float re = k[3 * kh] + k[3 * kh + 1] * c1 + k[3 * kh + 2] * c2;
            float im = k[3 * kh + 1] * s1 + k[3 * kh + 2] * s2;
            g_G[base + kh * 4096 + e] = make_float2(re, im);
        }
    }
}

// ---------------------------------------------------------------------------
// Kernel 2: circular conv (unchanged — known good, ~30us)
// ---------------------------------------------------------------------------
__global__ __launch_bounds__(256) void conv_kernel(const float* __restrict__ x,
                                                   const float* __restrict__ K,
                                                   const float* __restrict__ bias,
                                                   float* __restrict__ out) {
    __shared__ float sIn[66 * 68];
    __shared__ float sTap[9];
    int co = blockIdx.x;
    int b  = blockIdx.y;
    int tid = threadIdx.x;
    int ty = tid >> 4, tx = tid & 15;
    int py = ty * 4, px = tx * 4;

    float acc[4][4];
#pragma unroll
    for (int r = 0; r < 4; r++)
#pragma unroll
        for (int c = 0; c < 4; c++) acc[r][c] = 0.0f;

    for (int ci = 0; ci < 64; ci++) {
        __syncthreads();
        const float* xp = x + (size_t)(b * 64 + ci) * 4096;
        for (int e = tid; e < 66 * 66; e += 256) {
            int rr = e / 66;
            int cc2 = e - rr * 66;
            int gy = (rr + 63) & 63;
            int gx = (cc2 + 63) & 63;
            sIn[rr * 68 + cc2] = xp[gy * 64 + gx];
        }
        if (tid < 9) {
            float t = K[((size_t)(b * 64 + co) * 64 + ci) * 9 + tid];
            if (ci == co && tid == 4) t += 1.0f;
            sTap[tid] = t;
        }
        __syncthreads();
        float tp[9];
#pragma unroll
        for (int t = 0; t < 9; t++) tp[t] = sTap[t];
        float patch[6][6];
#pragma unroll
        for (int dr = 0; dr < 6; dr++)
#pragma unroll
            for (int dc = 0; dc < 6; dc++)
                patch[dr][dc] = sIn[(py + dr) * 68 + px + dc];
#pragma unroll
        for (int r = 0; r < 4; r++)
#pragma unroll
            for (int c = 0; c < 4; c++) {
                float a = acc[r][c];
#pragma unroll
                for (int kh = 0; kh < 3; kh++)
#pragma unroll
                    for (int kw = 0; kw < 3; kw++)
                        a = fmaf(tp[kh * 3 + kw], patch[r + kh][c + kw], a);
                acc[r][c] = a;
            }
    }
    float bv = bias[b * 64 + co];
    float* op = out + (size_t)(b * 64 + co) * 4096;
#pragma unroll
    for (int r = 0; r < 4; r++)
#pragma unroll
        for (int c = 0; c < 4; c++)
            op[(py + r) * 64 + px + c] = acc[r][c] + bv;
}

// ---------------------------------------------------------------------------
// Kernel 3: complex 64x64 LU, 256 threads, thread (ty,tx) owns 4x4 tile
// at rows 4ty.., cols 4tx.. (R2 layout — low reg pressure).
// 2 barriers/step, packed-key pivot reduce by all threads, log at end.
// ---------------------------------------------------------------------------
struct LuS {
    ull   colRaw[2][64];
    ull   rowV[2][64];
    ull   rowK[2][64];
    ull   candKey[2][16];
    float pivN2[64];
    float red[64];
};

__global__ __launch_bounds__(256, 3) void lu_kernel() {
    int u = blockIdx.x, v = blockIdx.y, b = blockIdx.z;
    int tid = threadIdx.x;
    int ty = tid >> 4, tx = tid & 15;
    int w  = tid >> 5;           // warp owns rows 8w..8w+7

    int uc = (64 - u) & 63, vc = (64 - v) & 63;
    bool canon = (u < uc) || (u == uc && v <= vc);
    if (!canon) {
        if (tid == 0) g_part[b * 4096 + u * 64 + v] = 0.0f;
        return;
    }
    float weight = (u == uc && v == vc) ? 1.0f : 2.0f;

    __shared__ LuS sm;

    // ---- build A = sum_kh G[b,v,kh] * wu^kh straight into registers ----
    const float2* __restrict__ Gb = g_G + (long long)((b * 64 + v) * 3) * 4096;
    float su, cu;
    sincosf(-6.283185307179586f * (float)u / 64.0f, &su, &cu);
    float cu2 = cu * cu - su * su;
    float su2 = 2.0f * su * cu;

    ull acc[4][4];
#pragma unroll
    for (int r = 0; r < 4; r++)
#pragma unroll
        for (int c = 0; c < 4; c++) {
            int e = (4 * ty + r) * 64 + 4 * tx + c;
            float2 g0 = Gb[e];
            float2 g1 = Gb[4096 + e];
            float2 g2 = Gb[8192 + e];
            float re = g0.x + cu * g1.x - su * g1.y + cu2 * g2.x - su2 * g2.y;
            float im = g0.y + cu * g1.y + su * g1.x + cu2 * g2.y + su2 * g2.x;
            acc[r][c] = pk2(re, im);
        }

    for (int k = 0; k < 64; k++) {
        int pb = k & 1;
        int c8 = k >> 2;     // owning tx
        int kc = k & 3;      // column within tile
        int kty = k >> 2;    // owning ty of row k
        int krl = k & 3;     // row within tile

        // ---- S1: column owners publish raw column + packed pivot candidates;
        //          row-k owners stage old row k.  (independent of p)
        if (tx == c8) {
            ull bestKey = 0ull;
#pragma unroll
            for (int r = 0; r < 4; r++) {
                int i = 4 * ty + r;
                ull vk = sel4(acc[r][0], acc[r][1], acc[r][2], acc[r][3], kc);
                sm.colRaw[pb][i] = vk;
                float re, im;
                upk2(vk, re, im);
                float n2 = fmaf(re, re, im * im);
                ull key = ((ull)__float_as_uint(n2) << 32) | (ull)(64 - i);
                if (i >= k && key > bestKey) bestKey = key;
            }
            sm.candKey[pb][ty] = bestKey;
        }
        if (ty == kty) {
#pragma unroll
            for (int r = 0; r < 4; r++)
                if (r == krl) {
#pragma unroll
                    for (int c = 0; c < 4; c++)
                        sm.rowK[pb][4 * tx + c] = acc[r][c];
                }
        }
        __syncthreads();   // B1

        // ---- S2: every thread reduces 16 keys; row-p owner publishes pivot row
        ull bk = sm.candKey[pb][0];
#pragma unroll
        for (int t = 1; t < 16; t++) {
            ull o = sm.candKey[pb][t];
            if (o > bk) bk = o;
        }
        int p = 64 - (int)(bk & 0xffffffffull);
        float bn = __uint_as_float((unsigned)(bk >> 32));   // |pivot|^2

        if (ty == (p >> 2)) {
            int pl = p & 3;
#pragma unroll
            for (int r = 0; r < 4; r++)
                if (r == pl) {
#pragma unroll
                    for (int c = 0; c < 4; c++)
                        sm.rowV[pb][4 * tx + c] = acc[r][c];
                }
        }
        if (tid == 0) sm.pivN2[k] = bn;
        __syncthreads();   // B2

        // ---- S3: register swap, multipliers from colRaw, rank-1 update
        if (ty == kty) {
#pragma unroll
            for (int r = 0; r < 4; r++)
                if (r == krl) {
#pragma unroll
                    for (int c = 0; c < 4; c++)
                        acc[r][c] = sm.rowV[pb][4 * tx + c];
                }
        }
        if (p != k && ty == (p >> 2)) {
            int pl = p & 3;
#pragma unroll
            for (int r = 0; r < 4; r++)
                if (r == pl) {
#pragma unroll
                    for (int c = 0; c < 4; c++)
                        acc[r][c] = sm.rowK[pb][4 * tx + c];
                }
        }

        if (8 * w + 7 > k) {   // warp-uniform: any of my rows still active?
            float pre, pim;
            upk2(sm.colRaw[pb][p], pre, pim);
            float inv = __fdividef(1.0f, bn);
            float ipre = pre * inv, ipim = -pim * inv;   // 1/pivot

            ull rv[4];
            float vr[4], vi[4];
#pragma unroll
            for (int c = 0; c < 4; c++) {
                rv[c] = sm.rowV[pb][4 * tx + c];
                upk2(rv[c], vr[c], vi[c]);
            }
            float akr, aki;
            upk2(sm.colRaw[pb][k], akr, aki);
#pragma unroll
            for (int r = 0; r < 4; r++) {
                int i = 4 * ty + r;
                float nre, nim;
                upk2(sm.colRaw[pb][i], nre, nim);
                if (i == p) { nre = akr; nim = aki; }   // post-swap value
                float mr = nre * ipre - nim * ipim;
                float mi = nre * ipim + nim * ipre;
                if (i <= k) { mr = 0.0f; mi = 0.0f; }
                ull mrd = pk2(-mr, -mr);
                ull mid = pk2(mi, mi);
#pragma unroll
                for (int c = 0; c < 4; c++) {
                    acc[r][c] = fma2(mrd, rv[c], acc[r][c]);
                    acc[r][c] = fma2(mid, pk2(vi[c], -vr[c]), acc[r][c]);
                }
            }
        }
    }

    // ---- log reduce (off the per-step critical path) ----
    __syncthreads();
    if (tid < 64) sm.red[tid] = logf(sm.pivN2[tid]);
    __syncthreads();
    if (tid == 0) {
        float s = 0.0f;
#pragma unroll
        for (int t = 0; t < 64; t++) s += sm.red[t];
        g_part[b * 4096 + u * 64 + v] = weight * 0.5f * s;
    }
}

// ---------------------------------------------------------------------------
// Kernel 4: reduce per-frequency partials -> logdet[b]
// ---------------------------------------------------------------------------
__global__ __launch_bounds__(256) void reduce_kernel(float* __restrict__ out) {
    __shared__ double red[256];
    int b = blockIdx.x;
    double s = 0.0;
    for (int e = threadIdx.x; e < 4096; e += 256)
        s += (double)g_part[b * 4096 + e];
    red[threadIdx.x] = s;
    __syncthreads();
    for (int st = 128; st > 0; st >>= 1) {
        if (threadIdx.x < st) red[threadIdx.x] += red[threadIdx.x + st];
        __syncthreads();
    }
    if (threadIdx.x == 0) out[1048576 + b] = (float)red[0];
}

// ---------------------------------------------------------------------------
extern "C" void kernel_launch(void* const* d_in, const int* in_sizes, int n_in,
                              void* d_out, int out_size) {
    const float* x = nullptr;
    const float* K = nullptr;
    const float* bias = nullptr;
    for (int i = 0; i < n_in; i++) {
        if (in_sizes[i] == 1048576)      x    = (const float*)d_in[i];
        else if (in_sizes[i] == 147456)  K    = (const float*)d_in[i];
        else if (in_sizes[i] == 256)     bias = (const float*)d_in[i];
    }
    float* out = (float*)d_out;

    gbuild_kernel<<<256, 256>>>(K);
    conv_kernel<<<dim3(64, 4), 256>>>(x, K, bias, out);
    lu_kernel<<<dim3(64, 64, 4), 256>>>();
    reduce_kernel<<<4, 256>>>(out);
}

// round 13
// speedup vs baseline: 1.2574x; 1.2574x over previous
#include <cuda_runtime.h>
#include <cuda_bf16.h>
#include <math.h>

#define BB 4
#define CC 64
#define NN 64

typedef unsigned long long ull;

// ---------------------------------------------------------------------------
// Device scratch
// ---------------------------------------------------------------------------
__device__ float2 g_G[BB * NN * 3 * CC * CC];   // 25.2 MB: G[b][v][kh][i][j]
__device__ float  g_part[BB * NN * NN];         // weighted per-frequency logdets
                                                // (zero-init; only canonical slots written)

// ---------------------------------------------------------------------------
// f32x2 packed helpers
// ---------------------------------------------------------------------------
__device__ __forceinline__ ull pk2(float lo, float hi) {
    ull r; asm("mov.b64 %0, {%1,%2};" : "=l"(r) : "f"(lo), "f"(hi)); return r;
}
__device__ __forceinline__ void upk2(ull v, float &lo, float &hi) {
    asm("mov.b64 {%0,%1}, %2;" : "=f"(lo), "=f"(hi) : "l"(v));
}
__device__ __forceinline__ ull fma2(ull a, ull b, ull c) {
    ull r; asm("fma.rn.f32x2 %0, %1, %2, %3;" : "=l"(r) : "l"(a), "l"(b), "l"(c));
    return r;
}
__device__ __forceinline__ ull sel4(ull a0, ull a1, ull a2, ull a3, int s) {
    ull x01 = (s & 1) ? a1 : a0;
    ull x23 = (s & 1) ? a3 : a2;
    return (s & 2) ? x23 : x01;
}

// ---------------------------------------------------------------------------
// Kernel 1: G build. G[b,v,kh,i,j] = sum_kw Kfull[b,i,j,kh,kw] * e^{-2pi i v kw/64}
// ---------------------------------------------------------------------------
__global__ __launch_bounds__(256) void gbuild_kernel(const float* __restrict__ K) {
    int v = blockIdx.x & 63;
    int b = blockIdx.x >> 6;
    float th = -6.283185307179586f * (float)v / 64.0f;
    float s1, c1;
    sincosf(th, &s1, &c1);
    float c2 = c1 * c1 - s1 * s1;
    float s2 = 2.0f * s1 * c1;
    long long base = ((long long)(b * 64 + v)) * 3 * 4096;
    for (int e = threadIdx.x; e < 4096; e += 256) {
        int i = e >> 6, j = e & 63;
        const float* kp = K + ((size_t)(b * 64 + i) * 64 + j) * 9;
        float k[9];
#pragma unroll
        for (int t = 0; t < 9; t++) k[t] = kp[t];
        if (i == j) k[4] += 1.0f;
#pragma unroll
        for (int kh = 0; kh < 3; kh++) {
            float re = k[3 * kh] + k[3 * kh + 1] * c1 + k[3 * kh + 2] * c2;
            float im = k[3 * kh + 1] * s1 + k[3 * kh + 2] * s2;
            g_G[base + kh * 4096 + e] = make_float2(re, im);
        }
    }
}

// ---------------------------------------------------------------------------
// Kernel 2: circular conv (unchanged — known good)
// ---------------------------------------------------------------------------
__global__ __launch_bounds__(256) void conv_kernel(const float* __restrict__ x,
                                                   const float* __restrict__ K,
                                                   const float* __restrict__ bias,
                                                   float* __restrict__ out) {
    __shared__ float sIn[66 * 68];
    __shared__ float sTap[9];
    int co = blockIdx.x;
    int b  = blockIdx.y;
    int tid = threadIdx.x;
    int ty = tid >> 4, tx = tid & 15;
    int py = ty * 4, px = tx * 4;

    float acc[4][4];
#pragma unroll
    for (int r = 0; r < 4; r++)
#pragma unroll
        for (int c = 0; c < 4; c++) acc[r][c] = 0.0f;

    for (int ci = 0; ci < 64; ci++) {
        __syncthreads();
        const float* xp = x + (size_t)(b * 64 + ci) * 4096;
        for (int e = tid; e < 66 * 66; e += 256) {
            int rr = e / 66;
            int cc2 = e - rr * 66;
            int gy = (rr + 63) & 63;
            int gx = (cc2 + 63) & 63;
            sIn[rr * 68 + cc2] = xp[gy * 64 + gx];
        }
        if (tid < 9) {
            float t = K[((size_t)(b * 64 + co) * 64 + ci) * 9 + tid];
            if (ci == co && tid == 4) t += 1.0f;
            sTap[tid] = t;
        }
        __syncthreads();
        float tp[9];
#pragma unroll
        for (int t = 0; t < 9; t++) tp[t] = sTap[t];
        float patch[6][6];
#pragma unroll
        for (int dr = 0; dr < 6; dr++)
#pragma unroll
            for (int dc = 0; dc < 6; dc++)
                patch[dr][dc] = sIn[(py + dr) * 68 + px + dc];
#pragma unroll
        for (int r = 0; r < 4; r++)
#pragma unroll
            for (int c = 0; c < 4; c++) {
                float a = acc[r][c];
#pragma unroll
                for (int kh = 0; kh < 3; kh++)
#pragma unroll
                    for (int kw = 0; kw < 3; kw++)
                        a = fmaf(tp[kh * 3 + kw], patch[r + kh][c + kw], a);
                acc[r][c] = a;
            }
    }
    float bv = bias[b * 64 + co];
    float* op = out + (size_t)(b * 64 + co) * 4096;
#pragma unroll
    for (int r = 0; r < 4; r++)
#pragma unroll
        for (int c = 0; c < 4; c++)
            op[(py + r) * 64 + px + c] = acc[r][c] + bv;
}

// ---------------------------------------------------------------------------
// Kernel 3: complex 64x64 LU. 128 threads (4 warps, nw=4 barriers).
// warp w owns rows 16w..16w+15; lane l: rg=l&3 -> rows 16w+4rg..+3,
// cg=l>>2 -> cols 8cg..8cg+7. acc[4][8] packed f32x2 (64 regs payload).
// NO register cap (avoid R3/R12 spill regressions). 2 barriers/step.
// Compact canonical grid: 2050 frequencies per sample.
// ---------------------------------------------------------------------------
struct LuS {
    ull   colRaw[2][64];
    ull   rowV[2][64];
    ull   rowK[2][64];
    ull   candKey[2][4];
    float pivN2[64];
    float red[64];
};

__global__ __launch_bounds__(128) void lu_kernel() {
    int b = blockIdx.y;
    int c = blockIdx.x;
    int u, v;
    float weight;
    if (c < 1984)      { u = 1 + (c >> 6); v = c & 63; weight = 2.0f; }
    else if (c < 2017) { u = 0;  v = c - 1984; weight = (v == 0 || v == 32) ? 1.0f : 2.0f; }
    else               { u = 32; v = c - 2017; weight = (v == 0 || v == 32) ? 1.0f : 2.0f; }

    int tid = threadIdx.x;
    int w  = tid >> 5;
    int l  = tid & 31;
    int rg = l & 3;
    int cg = l >> 2;

    __shared__ union {
        float2 A[4096];
        LuS bf;
    } sm;

    // ---- build A = sum_kh G[b,v,kh] * wu^kh (coalesced), stage via smem ----
    const float2* __restrict__ Gb = g_G + (long long)((b * 64 + v) * 3) * 4096;
    float su, cu;
    sincosf(-6.283185307179586f * (float)u / 64.0f, &su, &cu);
    float cu2 = cu * cu - su * su;
    float su2 = 2.0f * su * cu;

#pragma unroll 4
    for (int e = tid; e < 4096; e += 128) {
        float2 g0 = Gb[e];
        float2 g1 = Gb[4096 + e];
        float2 g2 = Gb[8192 + e];
        float re = g0.x + cu * g1.x - su * g1.y + cu2 * g2.x - su2 * g2.y;
        float im = g0.y + cu * g1.y + su * g1.x + cu2 * g2.y + su2 * g2.x;
        sm.A[e] = make_float2(re, im);
    }
    __syncthreads();

    ull acc[4][8];
#pragma unroll
    for (int r = 0; r < 4; r++) {
        int row = 16 * w + 4 * rg + r;
#pragma unroll
        for (int cc2 = 0; cc2 < 8; cc2++) {
            float2 t = sm.A[row * 64 + 8 * cg + cc2];
            acc[r][cc2] = pk2(t.x, t.y);
        }
    }
    __syncthreads();   // smem becomes LuS

    for (int k = 0; k < 64; k++) {
        int pb  = k & 1;
        int c8  = k >> 3;          // owning cg of column k
        int kc  = k & 7;           // col within tile
        int kw_ = k >> 4;          // owning warp of row k
        int krg = (k >> 2) & 3;    // owning rg
        int krl = k & 3;           // row within thread tile

        // ---- S1: column owners publish raw col + packed pivot keys;
        //          row-k owners stage old row k. (no pivot index needed)
        if (cg == c8) {
            ull bestKey = 0ull;
#pragma unroll
            for (int r = 0; r < 4; r++) {
                int i = 16 * w + 4 * rg + r;
                ull vkl = sel4(acc[r][0], acc[r][1], acc[r][2], acc[r][3], kc & 3);
                ull vkh = sel4(acc[r][4], acc[r][5], acc[r][6], acc[r][7], kc & 3);
                ull vk = (kc & 4) ? vkh : vkl;
                sm.bf.colRaw[pb][i] = vk;
                float re, im;
                upk2(vk, re, im);
                float n2 = fmaf(re, re, im * im);
                ull key = ((ull)__float_as_uint(n2) << 32) | (ull)(64 - i);
                if (i >= k && key > bestKey) bestKey = key;
            }
            unsigned mask = 0xFu << (4 * c8);
#pragma unroll
            for (int off = 1; off <= 2; off <<= 1) {
                ull o = __shfl_xor_sync(mask, bestKey, off, 4);
                if (o > bestKey) bestKey = o;
            }
            if (rg == 0) sm.bf.candKey[pb][w] = bestKey;
        }
        if (w == kw_ && rg == krg) {
#pragma unroll
            for (int r = 0; r < 4; r++)
                if (r == krl) {
#pragma unroll
                    for (int cc2 = 0; cc2 < 8; cc2++)
                        sm.bf.rowK[pb][8 * cg + cc2] = acc[r][cc2];
                }
        }
        __syncthreads();   // B1

        // ---- S2: all threads reduce 4 keys; row-p owner publishes pivot row
        ull bk = sm.bf.candKey[pb][0];
#pragma unroll
        for (int t = 1; t < 4; t++) {
            ull o = sm.bf.candKey[pb][t];
            if (o > bk) bk = o;
        }
        int p = 64 - (int)(bk & 0xffffffffull);
        float bn = __uint_as_float((unsigned)(bk >> 32));   // |pivot|^2

        if (w == (p >> 4) && rg == ((p >> 2) & 3)) {
            int pl = p & 3;
#pragma unroll
            for (int r = 0; r < 4; r++)
                if (r == pl) {
#pragma unroll
                    for (int cc2 = 0; cc2 < 8; cc2++)
                        sm.bf.rowV[pb][8 * cg + cc2] = acc[r][cc2];
                }
        }
        if (tid == 0) sm.bf.pivN2[k] = bn;
        __syncthreads();   // B2

        // ---- S3: register row swap, multipliers from colRaw, rank-1 update
        if (w == kw_ && rg == krg) {
#pragma unroll
            for (int r = 0; r < 4; r++)
                if (r == krl) {
#pragma unroll
                    for (int cc2 = 0; cc2 < 8; cc2++)
                        acc[r][cc2] = sm.bf.rowV[pb][8 * cg + cc2];
                }
        }
        if (p != k && w == (p >> 4) && rg == ((p >> 2) & 3)) {
            int pl = p & 3;
#pragma unroll
            for (int r = 0; r < 4; r++)
                if (r == pl) {
#pragma unroll
                    for (int cc2 = 0; cc2 < 8; cc2++)
                        acc[r][cc2] = sm.bf.rowK[pb][8 * cg + cc2];
                }
        }

        if (16 * w + 15 > k) {   // warp-uniform row guard
            ull rv[8], rs[8];
#pragma unroll
            for (int cc2 = 0; cc2 < 8; cc2++) {
                rv[cc2] = sm.bf.rowV[pb][8 * cg + cc2];
                float vr, vi;
                upk2(rv[cc2], vr, vi);
                rs[cc2] = pk2(vi, -vr);
            }
            float pre, pim;
            upk2(sm.bf.colRaw[pb][p], pre, pim);
            float inv = __fdividef(1.0f, bn);
            float ipre = pre * inv, ipim = -pim * inv;
            float akr, aki;
            upk2(sm.bf.colRaw[pb][k], akr, aki);
#pragma unroll
            for (int r = 0; r < 4; r++) {
                int i = 16 * w + 4 * rg + r;
                float nre, nim;
                upk2(sm.bf.colRaw[pb][i], nre, nim);
                if (i == p) { nre = akr; nim = aki; }
                float mr = nre * ipre - nim * ipim;
                float mi = nre * ipim + nim * ipre;
                if (i <= k) { mr = 0.0f; mi = 0.0f; }
                ull mrd = pk2(-mr, -mr);
                ull mid = pk2(mi, mi);
#pragma unroll
                for (int cc2 = 0; cc2 < 8; cc2++) {
                    acc[r][cc2] = fma2(mrd, rv[cc2], acc[r][cc2]);
                    acc[r][cc2] = fma2(mid, rs[cc2], acc[r][cc2]);
                }
            }
        }
    }

    // ---- log reduce (off critical path) ----
    __syncthreads();
    if (tid < 64) sm.bf.red[tid] = logf(sm.bf.pivN2[tid]);
    __syncthreads();
    if (tid == 0) {
        float s = 0.0f;
#pragma unroll
        for (int t = 0; t < 64; t++) s += sm.bf.red[t];
        g_part[b * 4096 + u * 64 + v] = weight * 0.5f * s;
    }
}

// ---------------------------------------------------------------------------
// Kernel 4: reduce per-frequency partials -> logdet[b]
// (non-canonical slots of g_part are never written and stay 0)
// ---------------------------------------------------------------------------
__global__ __launch_bounds__(256) void reduce_kernel(float* __restrict__ out) {
    __shared__ double red[256];
    int b = blockIdx.x;
    double s = 0.0;
    for (int e = threadIdx.x; e < 4096; e += 256)
        s += (double)g_part[b * 4096 + e];
    red[threadIdx.x] = s;
    __syncthreads();
    for (int st = 128; st > 0; st >>= 1) {
        if (threadIdx.x < st) red[threadIdx.x] += red[threadIdx.x + st];
        __syncthreads();
    }
    if (threadIdx.x == 0) out[1048576 + b] = (float)red[0];
}

// ---------------------------------------------------------------------------
extern "C" void kernel_launch(void* const* d_in, const int* in_sizes, int n_in,
                              void* d_out, int out_size) {
    const float* x = nullptr;
    const float* K = nullptr;
    const float* bias = nullptr;
    for (int i = 0; i < n_in; i++) {
        if (in_sizes[i] == 1048576)      x    = (const float*)d_in[i];
        else if (in_sizes[i] == 147456)  K    = (const float*)d_in[i];
        else if (in_sizes[i] == 256)     bias = (const float*)d_in[i];
    }
    float* out = (float*)d_out;

    gbuild_kernel<<<256, 256>>>(K);
    conv_kernel<<<dim3(64, 4), 256>>>(x, K, bias, out);
    lu_kernel<<<dim3(2050, 4), 128>>>();
    reduce_kernel<<<4, 256>>>(out);
}